// round 12
// baseline (speedup 1.0000x reference)
#include <cuda_runtime.h>
#include <cuda_fp16.h>
#include <math.h>
#include <stdint.h>

#define NN 50000
#define NP 50048          // NN padded to 128
#define RR 6
#define EE 32768
#define HH 256
#define FF 16
#define KVO 272
#define KVP 320           // 272 padded to 64-multiple
#define NHD 8
#define HDD 32
#define RH 1536

typedef __half fp16;

#if defined(__CUDA_ARCH__) && (defined(__CUDA_ARCH_FEAT_SM103_ALL) \
    || (defined(__CUDA_ARCH_SPECIFIC__) && (__CUDA_ARCH_SPECIFIC__ == 1030)) \
    || (defined(__CUDA_ARCH_FAMILY_SPECIFIC__) && (__CUDA_ARCH_FAMILY_SPECIFIC__ == 1030)))
#define HAS_TC05 1
#else
#define HAS_TC05 0
#endif

// ---------------- scratch (device globals; zero-initialized at load) ----------------
__device__ __align__(1024) fp16 g_kvin[RR * EE * KVP];
__device__ __align__(1024) fp16 g_xd[RR * EE * HH];
__device__ __align__(1024) fp16 g_qe16[(size_t)RR * EE * HH];
__device__ __align__(1024) fp16 g_k16[(size_t)RR * EE * HH];
__device__ __align__(1024) fp16 g_v16[(size_t)RR * EE * HH];
__device__ float g_sc[RR * EE * NHD], g_m[RR * NN * NHD], g_denom[RR * NN * NHD];
__device__ float g_agg[(size_t)RR * NN * HH];
__device__ __align__(1024) fp16 g_aggh[(size_t)RR * NP * HH];
__device__ __align__(1024) fp16 g_rel[(size_t)NP * RH];
__device__ float g_hbuf[NP * HH];
__device__ float g_interw[NN * NHD];
__device__ __align__(1024) fp16 g_cat[NP * 2 * HH];
__device__ __align__(1024) fp16 g_pth[3 * NP * HH];
__device__ __align__(1024) fp16 g_stk[NP * 3 * HH];
__device__ __align__(1024) fp16 g_t16[3 * NP * (HH / 2)];
// transposed weights: [Ncol][Kpad]
__device__ __align__(1024) fp16 g_wqt[RR * HH * HH];
__device__ __align__(1024) fp16 g_wkt[RR * HH * KVP];
__device__ __align__(1024) fp16 g_wvt[RR * HH * KVP];
__device__ __align__(1024) fp16 g_wmt[RR * HH * HH];
__device__ __align__(1024) fp16 g_wir1t[HH * RH];
__device__ __align__(1024) fp16 g_wmpt[3 * HH * HH];
__device__ __align__(1024) fp16 g_wa1t[(HH/2) * HH];
__device__ __align__(1024) fp16 g_wct[HH * 2 * HH];

// ---------------- common helpers ----------------
__device__ __forceinline__ float gelu_exact(float x) {
    return 0.5f * x * (1.0f + erff(x * 0.7071067811865475f));
}
__device__ __forceinline__ void store4h(float4 v, fp16* p) {
    union { __half2 h[2]; uint2 u; } U;
    U.h[0] = __halves2half2(__float2half_rn(v.x), __float2half_rn(v.y));
    U.h[1] = __halves2half2(__float2half_rn(v.z), __float2half_rn(v.w));
    *(uint2*)p = U.u;
}
__device__ __forceinline__ float4 load4h(const fp16* p) {
    union { uint2 u; __half2 h[2]; } U;
    U.u = *(const uint2*)p;
    float4 r;
    float2 a = __half22float2(U.h[0]), b = __half22float2(U.h[1]);
    r.x = a.x; r.y = a.y; r.z = b.x; r.w = b.y;
    return r;
}
// dot of 8 halves (uint4 = 4 half2)
__device__ __forceinline__ float dot8h(uint4 qa, uint4 ka) {
    union { uint4 u; __half2 h[4]; } Q, K;
    Q.u = qa; K.u = ka;
    float s = 0.f;
#pragma unroll
    for (int i = 0; i < 4; i++) {
        float2 q = __half22float2(Q.h[i]), k = __half22float2(K.h[i]);
        s += q.x * k.x + q.y * k.y;
    }
    return s;
}
__device__ __forceinline__ void atomicMaxF(float* addr, float v) {
    int* ai = (int*)addr;
    int old = *ai;
    while (__int_as_float(old) < v) {
        int assumed = old;
        old = atomicCAS(ai, assumed, __float_as_int(v));
        if (old == assumed) break;
    }
}
__device__ __forceinline__ float block_sum256(float v, float* sm) {
    int lane = threadIdx.x & 31, w = threadIdx.x >> 5;
#pragma unroll
    for (int o = 16; o; o >>= 1) v += __shfl_xor_sync(0xffffffffu, v, o);
    if (lane == 0) sm[w] = v;
    __syncthreads();
    float r;
    if (threadIdx.x < 8) {
        float s = sm[threadIdx.x];
#pragma unroll
        for (int o = 4; o; o >>= 1) s += __shfl_xor_sync(0xffu, s, o);
        if (threadIdx.x == 0) sm[0] = s;
    }
    __syncthreads();
    r = sm[0];
    __syncthreads();
    return r;
}
__device__ __forceinline__ uint32_t smem_u32(const void* p) {
    uint32_t a;
    asm("{ .reg .u64 t; cvta.to.shared.u64 t, %1; cvt.u32.u64 %0, t; }" : "=r"(a) : "l"(p));
    return a;
}
#define CP_ASYNC16(dst, src) \
    asm volatile("cp.async.cg.shared.global [%0], [%1], 16;" :: "r"(dst), "l"(src))
#define CP_COMMIT() asm volatile("cp.async.commit_group;")
#define CP_WAIT1()  asm volatile("cp.async.wait_group 1;")
#define CP_WAIT0()  asm volatile("cp.async.wait_group 0;")

#if HAS_TC05
#define SWZ128(o) ((o) ^ (((o) >> 3) & 0x70))
__device__ __forceinline__ uint64_t mkdesc(uint32_t addr) {
    return ((uint64_t)2 << 61) | ((uint64_t)1 << 46) | ((uint64_t)64 << 32) |
           ((uint64_t)1 << 16) | ((addr >> 4) & 0x3FFF);
}
__device__ __forceinline__ void mma_f16_ss(uint32_t d, uint64_t ad, uint64_t bd,
                                           uint32_t idesc, bool acc) {
    uint32_t en = acc ? 1u : 0u;
    asm volatile(
        "{\n\t.reg .pred p;\n\tsetp.ne.u32 p, %5, 0;\n\t"
        "tcgen05.mma.cta_group::1.kind::f16 [%0], %1, %2, %3, {%4,%4,%4,%4}, p;\n\t}"
        :: "r"(d), "l"(ad), "l"(bd), "r"(idesc), "r"(0u), "r"(en) : "memory");
}
__device__ __forceinline__ void mbar_init(uint32_t mb, uint32_t cnt) {
    asm volatile("mbarrier.init.shared.b64 [%0], %1;" :: "r"(mb), "r"(cnt) : "memory");
}
__device__ __forceinline__ void mbar_wait(uint32_t mb, int parity) {
    asm volatile(
        "{\n\t.reg .pred P1;\n\t"
        "WL_%=:\n\t"
        "mbarrier.try_wait.parity.acquire.cta.shared::cta.b64 P1, [%0], %1, 0x989680;\n\t"
        "@P1 bra.uni WD_%=;\n\t"
        "bra.uni WL_%=;\n\t"
        "WD_%=:\n\t}"
        :: "r"(mb), "r"(parity) : "memory");
}
#define LDTM_X32(r, a) \
    asm volatile( \
        "tcgen05.ld.sync.aligned.32x32b.x32.b32 " \
        "{%0, %1, %2, %3, %4, %5, %6, %7, " \
        " %8, %9, %10, %11, %12, %13, %14, %15, " \
        " %16, %17, %18, %19, %20, %21, %22, %23, " \
        " %24, %25, %26, %27, %28, %29, %30, %31}, [%32];" \
        : "=r"((r)[0]),  "=r"((r)[1]),  "=r"((r)[2]),  "=r"((r)[3]), \
          "=r"((r)[4]),  "=r"((r)[5]),  "=r"((r)[6]),  "=r"((r)[7]), \
          "=r"((r)[8]),  "=r"((r)[9]),  "=r"((r)[10]), "=r"((r)[11]), \
          "=r"((r)[12]), "=r"((r)[13]), "=r"((r)[14]), "=r"((r)[15]), \
          "=r"((r)[16]), "=r"((r)[17]), "=r"((r)[18]), "=r"((r)[19]), \
          "=r"((r)[20]), "=r"((r)[21]), "=r"((r)[22]), "=r"((r)[23]), \
          "=r"((r)[24]), "=r"((r)[25]), "=r"((r)[26]), "=r"((r)[27]), \
          "=r"((r)[28]), "=r"((r)[29]), "=r"((r)[30]), "=r"((r)[31]) \
        : "r"(a))
#else
__device__ __forceinline__ void hmma16816(float* c, const uint32_t* a, const uint32_t* b) {
    asm volatile(
        "mma.sync.aligned.m16n8k16.row.col.f32.f16.f16.f32 "
        "{%0,%1,%2,%3}, {%4,%5,%6,%7}, {%8,%9}, {%0,%1,%2,%3};"
        : "+f"(c[0]), "+f"(c[1]), "+f"(c[2]), "+f"(c[3])
        : "r"(a[0]), "r"(a[1]), "r"(a[2]), "r"(a[3]), "r"(b[0]), "r"(b[1]));
}
#define LDSM_X4(r, addr) \
    asm volatile("ldmatrix.sync.aligned.m8n8.x4.shared.b16 {%0,%1,%2,%3}, [%4];" \
        : "=r"((r)[0]), "=r"((r)[1]), "=r"((r)[2]), "=r"((r)[3]) : "r"(addr))
#endif

// ---------------- fp16 GEMM (z-batched) ----------------
// Block tile 128x128; 64-K slabs; 2-stage cp.async; 3 CTAs/SM.
// STORE: 0 = fp32 C only; 1 = fp32 C + fp16; 2 = fp16 only.
template <int ACT, int STORE>
__global__ __launch_bounds__(256, 3)
void tcmm(const fp16* __restrict__ A, long az,
          const fp16* __restrict__ B, long bz,
          const float* __restrict__ bias, int biasz,
          float* __restrict__ C, int ldc, int coff, long cz, int coffz,
          fp16* __restrict__ Ch, int ldh, int offh, long chz, int offhz,
          int M, int K) {
    extern __shared__ char smem[];
    const int tid = threadIdx.x, wid = tid >> 5, lid = tid & 31;
    const int m0 = blockIdx.y * 128;
    const int n0 = blockIdx.x * 128;
    const int z = blockIdx.z;
    A += (size_t)z * az;
    B += (size_t)z * bz;
    bias += (size_t)z * biasz;
    if (STORE != 2) { C += (size_t)z * cz; coff += z * coffz; }
    if (STORE != 0) { Ch += (size_t)z * chz; offh += z * offhz; }

#if HAS_TC05
    // ================= tcgen05 path =================
    const uint32_t sb = smem_u32(smem);
    const int ABYTES = 128 * 128;
    const int BUF = 2 * ABYTES;
    const uint32_t mbar0 = sb + 8, mbar1 = sb + 16;
    const uint32_t buf0 = sb + 1024;

    if (wid == 0) {
        asm volatile("tcgen05.alloc.cta_group::1.sync.aligned.shared::cta.b32 [%0], %1;"
                     :: "r"(sb), "r"(128u) : "memory");
        asm volatile("tcgen05.relinquish_alloc_permit.cta_group::1.sync.aligned;");
    }
    __syncthreads();
    uint32_t tmem;
    asm volatile("ld.shared.b32 %0, [%1];" : "=r"(tmem) : "r"(sb));
    if (tid == 0) { mbar_init(mbar0, 1); mbar_init(mbar1, 1); }
    __syncthreads();

    const int T = K >> 6;
    const uint32_t idesc64 = (1u << 4) | (8u << 17) | (8u << 24);

    auto load_chunk = [&](int c, uint32_t bufbase) {
        int kc = c << 6;
        for (int i = tid; i < 2048; i += 256) {
            uint32_t dst;
            const fp16* src;
            if (i < 1024) {
                int r = i >> 3, g = i & 7;
                dst = bufbase + SWZ128(r * 128 + g * 16);
                src = A + (size_t)(m0 + r) * K + kc + g * 8;
            } else {
                int j = i - 1024;
                int r = j >> 3, g = j & 7;
                dst = bufbase + ABYTES + SWZ128(r * 128 + g * 16);
                src = B + (size_t)(n0 + r) * K + kc + g * 8;
            }
            CP_ASYNC16(dst, src);
        }
        CP_COMMIT();
    };

    int ph0 = 0, ph1 = 0;
    load_chunk(0, buf0);
    for (int c = 0; c < T; c++) {
        int b = c & 1;
        if (c + 1 < T) {
            int nb = b ^ 1;
            if (c >= 1) {
                if (nb) { mbar_wait(mbar1, ph1); ph1 ^= 1; }
                else    { mbar_wait(mbar0, ph0); ph0 ^= 1; }
            }
            load_chunk(c + 1, buf0 + nb * BUF);
            CP_WAIT1();
        } else {
            CP_WAIT0();
        }
        __syncthreads();
        if (tid == 0) {
            asm volatile("fence.proxy.async.shared::cta;" ::: "memory");
            uint64_t ad = mkdesc(buf0 + b * BUF);
            uint64_t bd = mkdesc(buf0 + b * BUF + ABYTES);
#pragma unroll
            for (int ks = 0; ks < 4; ks++)
#pragma unroll
                for (int ns = 0; ns < 2; ns++)
                    mma_f16_ss(tmem + ns * 64, ad + ks * 2, bd + ns * 512 + ks * 2,
                               idesc64, (c > 0) || (ks > 0));
            asm volatile("tcgen05.commit.cta_group::1.mbarrier::arrive::one.shared::cluster.b64 [%0];"
                         :: "r"(b ? mbar1 : mbar0) : "memory");
        }
    }
    {
        int lb = (T - 1) & 1;
        if (lb) mbar_wait(mbar1, ph1); else mbar_wait(mbar0, ph0);
    }
    asm volatile("tcgen05.fence::after_thread_sync;" ::: "memory");

    {
        int row = m0 + (wid & 3) * 32 + lid;
        int colbase = (wid >> 2) * 64;
        for (int cb = 0; cb < 64; cb += 32) {
            uint32_t regs[32];
            LDTM_X32(regs, tmem + colbase + cb);
            asm volatile("tcgen05.wait::ld.sync.aligned;" ::: "memory");
            if (row < M) {
#pragma unroll
                for (int j = 0; j < 32; j++) {
                    int col = n0 + colbase + cb + j;
                    float v = __uint_as_float(regs[j]) + bias[col];
                    if (ACT == 1) v = gelu_exact(v);
                    else if (ACT == 2) v = tanhf(v);
                    if (STORE != 2) C[(size_t)row * ldc + coff + col] = v;
                    if (STORE != 0) Ch[(size_t)row * ldh + offh + col] = __float2half_rn(v);
                }
            }
        }
    }
    __syncthreads();
    if (wid == 0)
        asm volatile("tcgen05.dealloc.cta_group::1.sync.aligned.b32 %0, %1;"
                     :: "r"(tmem), "r"(128u));

#else
    // ================= ldmatrix + mma.sync path =================
    const uint32_t sm_u = smem_u32(smem);
    const int STG = 36864;
    const int g = lid >> 2, tig = lid & 3;
    const int wr = wid >> 2, wc = wid & 3;
    const int rowbase = wr * 64, colbase = wc * 32;
    const int S = K >> 6;

    const uint32_t a_lane = (uint32_t)(rowbase + (lid & 15)) * 144 + ((lid >> 4) << 4);
    const uint32_t b_lane = (uint32_t)(colbase + (lid & 7) + (((lid >> 4) & 1) << 3)) * 144
                          + (((lid >> 3) & 1) << 4);

    auto load_stage = [&](int s, int buf) {
        int k0 = s << 6;
        uint32_t ab = sm_u + buf * STG, bb = ab + 18432;
#pragma unroll
        for (int rep = 0; rep < 4; rep++) {
            int i = tid + 256 * rep;
            int r = i >> 3, sc = i & 7;
            CP_ASYNC16(ab + r * 144 + sc * 16, A + (size_t)(m0 + r) * K + k0 + sc * 8);
        }
#pragma unroll
        for (int rep = 0; rep < 4; rep++) {
            int i = tid + 256 * rep;
            int r = i >> 3, sc = i & 7;
            CP_ASYNC16(bb + r * 144 + sc * 16, B + (size_t)(n0 + r) * K + k0 + sc * 8);
        }
        CP_COMMIT();
    };

    float acc[4][4][4];
#pragma unroll
    for (int mf = 0; mf < 4; mf++)
#pragma unroll
        for (int nf = 0; nf < 4; nf++)
#pragma unroll
            for (int q = 0; q < 4; q++) acc[mf][nf][q] = 0.f;

    load_stage(0, 0);
    for (int s = 0; s < S; s++) {
        if (s + 1 < S) { load_stage(s + 1, (s + 1) & 1); CP_WAIT1(); }
        else CP_WAIT0();
        __syncthreads();
        uint32_t ab = sm_u + (s & 1) * STG;
        uint32_t bb = ab + 18432;
#pragma unroll
        for (int kk = 0; kk < 64; kk += 16) {
            uint32_t afr[4][4], bfr[2][4];
#pragma unroll
            for (int mf = 0; mf < 4; mf++)
                LDSM_X4(afr[mf], ab + a_lane + mf * 2304 + kk * 2);
#pragma unroll
            for (int np = 0; np < 2; np++)
                LDSM_X4(bfr[np], bb + b_lane + np * 2304 + kk * 2);
#pragma unroll
            for (int mf = 0; mf < 4; mf++)
#pragma unroll
                for (int nf = 0; nf < 4; nf++)
                    hmma16816(acc[mf][nf], afr[mf], &bfr[nf >> 1][(nf & 1) * 2]);
        }
        __syncthreads();
    }

#pragma unroll
    for (int mf = 0; mf < 4; mf++)
#pragma unroll
        for (int nf = 0; nf < 4; nf++) {
            int col0 = n0 + colbase + nf * 8 + 2 * tig;
#pragma unroll
            for (int r8 = 0; r8 < 2; r8++) {
                int row = m0 + rowbase + mf * 16 + g + r8 * 8;
                if (row < M) {
#pragma unroll
                    for (int cc = 0; cc < 2; cc++) {
                        int col = col0 + cc;
                        float v = acc[mf][nf][r8 * 2 + cc] + bias[col];
                        if (ACT == 1) v = gelu_exact(v);
                        else if (ACT == 2) v = tanhf(v);
                        if (STORE != 2) C[(size_t)row * ldc + coff + col] = v;
                        if (STORE != 0) Ch[(size_t)row * ldh + offh + col] = __float2half_rn(v);
                    }
                }
            }
        }
#endif
}

// ---------------- fused weight transpose (ALL weights, 1 launch) ----------------
__global__ void tsplit_all(const float* __restrict__ Wq, const float* __restrict__ Wk,
                           const float* __restrict__ Wv, const float* __restrict__ Wm,
                           const float* __restrict__ Wir1, const float* __restrict__ Wmp,
                           const float* __restrict__ Wa1, const float* __restrict__ Wc) {
    int idx = blockIdx.x * blockDim.x + threadIdx.x;
    int seg = blockIdx.y;
    float v;
    switch (seg) {
    case 0: {
        if (idx >= RR * HH * HH) return;
        int z = idx >> 16, w = idx & 65535, n = w >> 8, k = w & 255;
        v = Wq[(size_t)z * 65536 + k * HH + n];
        g_wqt[idx] = __float2half_rn(v);
        break; }
    case 1: {
        if (idx >= RR * HH * KVP) return;
        int z = idx / 81920, w = idx - z * 81920, n = w / KVP, k = w - n * KVP;
        v = (k < KVO) ? Wk[(size_t)z * KVO * HH + k * HH + n] : 0.f;
        g_wkt[idx] = __float2half_rn(v);
        break; }
    case 2: {
        if (idx >= RR * HH * KVP) return;
        int z = idx / 81920, w = idx - z * 81920, n = w / KVP, k = w - n * KVP;
        v = (k < KVO) ? Wv[(size_t)z * KVO * HH + k * HH + n] : 0.f;
        g_wvt[idx] = __float2half_rn(v);
        break; }
    case 3: {
        if (idx >= RR * HH * HH) return;
        int z = idx >> 16, w = idx & 65535, n = w >> 8, k = w & 255;
        v = Wm[(size_t)z * 65536 + k * HH + n];
        g_wmt[idx] = __float2half_rn(v);
        break; }
    case 4: {
        if (idx >= HH * RH) return;
        int n = idx / RH, k = idx - n * RH;
        v = Wir1[(size_t)k * HH + n];
        g_wir1t[idx] = __float2half_rn(v);
        break; }
    case 5: {
        if (idx >= 3 * HH * HH) return;
        int z = idx >> 16, w = idx & 65535, n = w >> 8, k = w & 255;
        v = Wmp[(size_t)z * 65536 + k * HH + n];
        g_wmpt[idx] = __float2half_rn(v);
        break; }
    case 6: {
        if (idx >= (HH / 2) * HH) return;
        int n = idx >> 8, k = idx & 255;
        v = Wa1[(size_t)k * (HH / 2) + n];
        g_wa1t[idx] = __float2half_rn(v);
        break; }
    default: {
        if (idx >= HH * 2 * HH) return;
        int n = idx >> 9, k = idx & 511;
        v = Wc[(size_t)k * HH + n];
        g_wct[idx] = __float2half_rn(v);
        break; }
    }
}

// ---------------- fused fills (vectorized) ----------------
__global__ void fill_all() {
    const int T14 = RR * NN * NHD / 4;
    const long T24 = (long)RR * NN * HH / 4;
    long idx = (long)blockIdx.x * blockDim.x + threadIdx.x;
    if (idx < T14) {
        ((float4*)g_m)[idx] = make_float4(-INFINITY, -INFINITY, -INFINITY, -INFINITY);
        ((float4*)g_denom)[idx] = make_float4(0.f, 0.f, 0.f, 0.f);
    } else {
        long j = idx - T14;
        if (j < T24) ((float4*)g_agg)[j] = make_float4(0.f, 0.f, 0.f, 0.f);
    }
}

// ---------------- gather (vectorized float4 -> fp16x4) ----------------
__global__ void gather_split(const float* __restrict__ x, const int* __restrict__ ei,
                             const float* __restrict__ ea) {
    long idx = (long)blockIdx.x * blockDim.x + threadIdx.x;
    const long perR = (long)EE * (KVP / 4 + HH / 4);
    if (idx >= RR * perR) return;
    int r = (int)(idx / perR);
    long rem = idx - (long)r * perR;
    if (rem < (long)EE * (KVP / 4)) {
        int e = (int)(rem / (KVP / 4)), c4 = (int)(rem - (long)e * (KVP / 4));
        int src = ei[(r * 2 + 0) * EE + e];
        float4 v;
        if (c4 < 64)      v = ((const float4*)(x + (size_t)src * HH))[c4];
        else if (c4 < 68) v = ((const float4*)(ea + ((size_t)r * EE + e) * FF))[c4 - 64];
        else              v = make_float4(0.f, 0.f, 0.f, 0.f);
        store4h(v, g_kvin + ((size_t)r * EE + e) * KVP + 4 * c4);
    } else {
        long j = rem - (long)EE * (KVP / 4);
        int e = (int)(j >> 6), c4 = (int)(j & 63);
        int dst = ei[(r * 2 + 1) * EE + e];
        float4 v = ((const float4*)(x + (size_t)dst * HH))[c4];
        store4h(v, g_xd + ((size_t)r * EE + e) * HH + 4 * c4);
    }
}

// ---------------- scores: warp per (r, e), fp16 uint4 loads ----------------
// lane loads 8 halves covering d=[8*lane, 8*lane+8); head = lane>>2; reduce over 4 lanes
__global__ void scores_kernel(const int* __restrict__ ei, const float* __restrict__ prior) {
    int w = (blockIdx.x * blockDim.x + threadIdx.x) >> 5;
    int lane = threadIdx.x & 31;
    if (w >= RR * EE) return;
    int r = w >> 15, e = w & (EE - 1);
    const uint4* q4 = (const uint4*)(g_qe16 + ((size_t)r * EE + e) * HH);
    const uint4* k4 = (const uint4*)(g_k16  + ((size_t)r * EE + e) * HH);
    float p = dot8h(q4[lane], k4[lane]);
    p += __shfl_xor_sync(0xffffffff, p, 1);
    p += __shfl_xor_sync(0xffffffff, p, 2);
    if ((lane & 3) == 0) {
        int dst = ei[(r * 2 + 1) * EE + e];
        int h = lane >> 2;
        float s = p * 0.17677669529663687f * prior[r * NHD + h];
        g_sc[((size_t)r * EE + e) * NHD + h] = s;
        atomicMaxF(&g_m[((size_t)r * NN + dst) * NHD + h], s);
    }
}

__global__ void ex_kernel(const int* __restrict__ ei) {
    int idx = blockIdx.x * blockDim.x + threadIdx.x;
    if (idx >= RR * EE * NHD) return;
    int r = idx >> 18;
    int e = (idx >> 3) & (EE - 1), h = idx & 7;
    int dst = ei[(r * 2 + 1) * EE + e];
    float exv = expf(g_sc[idx] - g_m[((size_t)r * NN + dst) * NHD + h]);
    g_sc[idx] = exv;
    atomicAdd(&g_denom[((size_t)r * NN + dst) * NHD + h], exv);
}

// ---------------- aggregation (fp16 v, 4 atomics) ----------------
__global__ void agg_kernel(const int* __restrict__ ei) {
    long idx = (long)blockIdx.x * blockDim.x + threadIdx.x;
    if (idx >= (long)RR * EE * (HH / 4)) return;
    int r = (int)(idx >> 21);
    long w_ = idx & ((1L << 21) - 1);
    int e = (int)(w_ >> 6), c4 = (int)(w_ & 63);
    int h = c4 >> 3;
    int dst = ei[(r * 2 + 1) * EE + e];
    float w = g_sc[((size_t)r * EE + e) * NHD + h] /
              (g_denom[((size_t)r * NN + dst) * NHD + h] + 1e-16f);
    float4 vv = load4h(g_v16 + idx * 4);
    float* base = &g_agg[((size_t)r * NN + dst) * HH + 4 * c4];
    atomicAdd(base + 0, w * vv.x);
    atomicAdd(base + 1, w * vv.y);
    atomicAdd(base + 2, w * vv.z);
    atomicAdd(base + 3, w * vv.w);
}

__global__ void agg_split_kernel() {
    long idx = (long)blockIdx.x * blockDim.x + threadIdx.x;
    if (idx >= (long)RR * NN * (HH / 4)) return;
    int r = (int)(idx / ((long)NN * 64));
    long w_ = idx - (long)r * NN * 64;
    int n = (int)(w_ >> 6), c4 = (int)(w_ & 63);
    float4 v = ((const float4*)g_agg)[idx];
    store4h(v, g_aggh + ((size_t)r * NP + n) * HH + 4 * c4);
}

__global__ void interw_kernel(const float* __restrict__ Wir2, const float* __restrict__ bir2) {
    int gwarp = (blockIdx.x * blockDim.x + threadIdx.x) >> 5;
    int lane = threadIdx.x & 31;
    if (gwarp >= NN) return;
    float acc[RR] = {};
    for (int k = lane; k < HH; k += 32) {
        float hv = g_hbuf[gwarp * HH + k];
#pragma unroll
        for (int rr = 0; rr < RR; rr++) acc[rr] += hv * Wir2[k * RR + rr];
    }
#pragma unroll
    for (int rr = 0; rr < RR; rr++)
#pragma unroll
        for (int off = 16; off; off >>= 1)
            acc[rr] += __shfl_down_sync(0xffffffff, acc[rr], off);
    if (lane == 0) {
        float mx = -1e30f;
#pragma unroll
        for (int rr = 0; rr < RR; rr++) { acc[rr] += bir2[rr]; mx = fmaxf(mx, acc[rr]); }
        float s = 0.f;
#pragma unroll
        for (int rr = 0; rr < RR; rr++) { acc[rr] = expf(acc[rr] - mx); s += acc[rr]; }
        float inv = 1.f / s;
#pragma unroll
        for (int rr = 0; rr < RR; rr++) g_interw[gwarp * NHD + rr] = acc[rr] * inv;
    }
}

// fused interagg + paths (vectorized)
__global__ void postrel_kernel() {
    int idx = blockIdx.x * blockDim.x + threadIdx.x;
    if (idx >= NN * (HH / 4)) return;
    int n = idx >> 6, c4 = idx & 63;
    float4 v[RR];
#pragma unroll
    for (int rr = 0; rr < RR; rr++)
        v[rr] = load4h(g_rel + (size_t)n * RH + rr * HH + 4 * c4);
    float4 s = make_float4(0.f, 0.f, 0.f, 0.f);
#pragma unroll
    for (int rr = 0; rr < RR; rr++) {
        float w = g_interw[n * NHD + rr];
        s.x += w * v[rr].x; s.y += w * v[rr].y; s.z += w * v[rr].z; s.w += w * v[rr].w;
    }
    store4h(s, g_cat + (size_t)n * 2 * HH + 4 * c4);
    float4 p0 = make_float4(v[2].x + v[3].x, v[2].y + v[3].y, v[2].z + v[3].z, v[2].w + v[3].w);
    float4 p1 = make_float4(v[4].x + v[0].x, v[4].y + v[0].y, v[4].z + v[0].z, v[4].w + v[0].w);
    float4 p2 = make_float4(v[1].x + v[5].x, v[1].y + v[5].y, v[1].z + v[5].z, v[1].w + v[5].w);
    store4h(p0, g_pth + ((size_t)0 * NP + n) * HH + 4 * c4);
    store4h(p1, g_pth + ((size_t)1 * NP + n) * HH + 4 * c4);
    store4h(p2, g_pth + ((size_t)2 * NP + n) * HH + 4 * c4);
}

__global__ void attnmeta_kernel(const float* __restrict__ Wa2,
                                const float* __restrict__ gm, const float* __restrict__ bm_) {
    __shared__ float lg[3];
    __shared__ float sm[8];
    int n = blockIdx.x, t = threadIdx.x;
    int lane = t & 31, w = t >> 5;
    if (w < 3) {
        float a = 0.f;
        for (int j = lane; j < 128; j += 32)
            a += __half2float(g_t16[((size_t)n * 3 + w) * 128 + j]) * Wa2[j];
#pragma unroll
        for (int off = 16; off; off >>= 1) a += __shfl_down_sync(0xffffffff, a, off);
        if (lane == 0) lg[w] = a;
    }
    __syncthreads();
    float l0 = lg[0], l1 = lg[1], l2 = lg[2];
    float mx = fmaxf(l0, fmaxf(l1, l2));
    float e0 = expf(l0 - mx), e1 = expf(l1 - mx), e2 = expf(l2 - mx);
    float inv = 1.f / (e0 + e1 + e2);
    const fp16* st = g_stk + (size_t)n * 3 * HH;
    float s = (e0 * __half2float(st[t]) + e1 * __half2float(st[HH + t])
             + e2 * __half2float(st[2 * HH + t])) * inv;
    float mu = block_sum256(s, sm) * (1.f / 256.f);
    float d = s - mu;
    float var = block_sum256(d * d, sm) * (1.f / 256.f);
    float o = d * rsqrtf(var + 1e-5f) * gm[t] + bm_[t];
    g_cat[(size_t)n * 2 * HH + HH + t] = __float2half_rn(o);
}

__global__ void outln_kernel(const float* __restrict__ x, const float* __restrict__ gout,
                             const float* __restrict__ bout, float* __restrict__ out) {
    __shared__ float sm[8];
    int n = blockIdx.x, t = threadIdx.x;
    float v = x[(size_t)n * HH + t] + g_hbuf[(size_t)n * HH + t];
    float mu = block_sum256(v, sm) * (1.f / 256.f);
    float d = v - mu;
    float var = block_sum256(d * d, sm) * (1.f / 256.f);
    out[(size_t)n * HH + t] = d * rsqrtf(var + 1e-5f) * gout[t] + bout[t];
}

// ---------------- host ----------------
extern "C" void kernel_launch(void* const* d_in, const int* in_sizes, int n_in,
                              void* d_out, int out_size) {
    const float* x     = (const float*)d_in[0];
    const int*   ei    = (const int*)d_in[1];
    const float* ea    = (const float*)d_in[2];
    const float* Wq    = (const float*)d_in[3];
    const float* bq    = (const float*)d_in[4];
    const float* Wk    = (const float*)d_in[5];
    const float* bk    = (const float*)d_in[6];
    const float* Wv    = (const float*)d_in[7];
    const float* bv    = (const float*)d_in[8];
    const float* prior = (const float*)d_in[9];
    const float* Wm    = (const float*)d_in[10];
    const float* bm    = (const float*)d_in[11];
    const float* W_ir1 = (const float*)d_in[12];
    const float* b_ir1 = (const float*)d_in[13];
    const float* W_ir2 = (const float*)d_in[14];
    const float* b_ir2 = (const float*)d_in[15];
    const float* Wmp   = (const float*)d_in[16];
    const float* bmp   = (const float*)d_in[17];
    const float* Wa1   = (const float*)d_in[18];
    const float* ba1   = (const float*)d_in[19];
    const float* Wa2   = (const float*)d_in[20];
    const float* gmeta = (const float*)d_in[21];
    const float* bmeta = (const float*)d_in[22];
    const float* Wc    = (const float*)d_in[23];
    const float* bc    = (const float*)d_in[24];
    const float* gout  = (const float*)d_in[25];
    const float* bout  = (const float*)d_in[26];
    float* out = (float*)d_out;

    void* p;
#define SYM(v, s) cudaGetSymbolAddress(&p, s); auto* v = (decltype(&s[0]))p
    SYM(p_kvin, g_kvin);
    SYM(p_xd, g_xd);
    SYM(p_qe16, g_qe16); SYM(p_k16, g_k16); SYM(p_v16, g_v16);
    SYM(p_aggh, g_aggh);
    SYM(p_rel, g_rel);
    SYM(p_hbuf, g_hbuf);
    SYM(p_cat, g_cat);
    SYM(p_pth, g_pth);
    SYM(p_stk, g_stk);
    SYM(p_t16, g_t16);
    SYM(p_wqt, g_wqt);
    SYM(p_wkt, g_wkt);
    SYM(p_wvt, g_wvt);
    SYM(p_wmt, g_wmt);
    SYM(p_wir1t, g_wir1t);
    SYM(p_wmpt, g_wmpt);
    SYM(p_wa1t, g_wa1t);
    SYM(p_wct, g_wct);
#undef SYM

    const int SMB = 73728;
    cudaFuncSetAttribute((const void*)&tcmm<0, 0>, cudaFuncAttributeMaxDynamicSharedMemorySize, SMB);
    cudaFuncSetAttribute((const void*)&tcmm<0, 2>, cudaFuncAttributeMaxDynamicSharedMemorySize, SMB);
    cudaFuncSetAttribute((const void*)&tcmm<1, 2>, cudaFuncAttributeMaxDynamicSharedMemorySize, SMB);
    cudaFuncSetAttribute((const void*)&tcmm<1, 0>, cudaFuncAttributeMaxDynamicSharedMemorySize, SMB);
    cudaFuncSetAttribute((const void*)&tcmm<2, 2>, cudaFuncAttributeMaxDynamicSharedMemorySize, SMB);

    const int TB = 256;
    fp16* nh = nullptr;
    float* nf32 = nullptr;

    // 0: weight transposes
    tsplit_all<<<dim3((RR * HH * KVP + TB - 1) / TB, 8), TB>>>(Wq, Wk, Wv, Wm, W_ir1, Wmp, Wa1, Wc);
    // 1: fills
    {
        long tot = (long)RR * NN * NHD / 4 + (long)RR * NN * HH / 4;
        fill_all<<<(int)((tot + TB - 1) / TB), TB>>>();
    }
    // 2: gather
    gather_split<<<(int)(((long)RR * EE * (KVP / 4 + HH / 4) + TB - 1) / TB), TB>>>(x, ei, ea);

    // 3,4,5: q/k/v GEMMs (fp16 outputs)
    tcmm<0, 2><<<dim3(2, EE / 128, RR), 256, SMB>>>(
        p_xd, (long)EE * HH,
        p_wqt, (long)HH * HH,
        bq, HH,
        nf32, 0, 0, 0, 0,
        p_qe16, HH, 0, (long)EE * HH, 0, EE, HH);
    tcmm<0, 2><<<dim3(2, EE / 128, RR), 256, SMB>>>(
        p_kvin, (long)EE * KVP,
        p_wkt, (long)HH * KVP,
        bk, HH,
        nf32, 0, 0, 0, 0,
        p_k16, HH, 0, (long)EE * HH, 0, EE, KVP);
    tcmm<0, 2><<<dim3(2, EE / 128, RR), 256, SMB>>>(
        p_kvin, (long)EE * KVP,
        p_wvt, (long)HH * KVP,
        bv, HH,
        nf32, 0, 0, 0, 0,
        p_v16, HH, 0, (long)EE * HH, 0, EE, KVP);

    // 6-9: attention softmax + aggregation
    scores_kernel<<<RR * EE / 8, TB>>>(ei, prior);
    ex_kernel<<<RR * EE * NHD / TB, TB>>>(ei);
    agg_kernel<<<(int)(((long)RR * EE * (HH / 4) + TB - 1) / TB), TB>>>(ei);
    agg_split_kernel<<<(int)(((long)RR * NN * (HH / 4) + TB - 1) / TB), TB>>>();

    // 10: Wm GEMM -> rel_out (fp16 only)
    tcmm<1, 2><<<dim3(2, NP / 128, RR), 256, SMB>>>(
        p_aggh, (long)NP * HH,
        p_wmt, (long)HH * HH,
        bm, HH,
        nf32, 0, 0, 0, 0,
        p_rel, RH, 0, 0, HH, NN, HH);

    // 11-13: inter-relation attention + fused post-rel
    tcmm<1, 0><<<dim3(2, NP / 128, 1), 256, SMB>>>(
        p_rel, 0,
        p_wir1t, 0,
        b_ir1, 0,
        p_hbuf, HH, 0, 0, 0,
        nh, 0, 0, 0, 0, NN, RH);
    interw_kernel<<<(NN * 32 + TB - 1) / TB, TB>>>(W_ir2, b_ir2);
    postrel_kernel<<<(NN * (HH / 4) + TB - 1) / TB, TB>>>();

    // 14-16: meta paths (fp16 outputs)
    tcmm<0, 2><<<dim3(2, NP / 128, 3), 256, SMB>>>(
        p_pth, (long)NP * HH,
        p_wmpt, (long)HH * HH,
        bmp, HH,
        nf32, 0, 0, 0, 0,
        p_stk, 3 * HH, 0, 0, HH, NN, HH);
    tcmm<2, 2><<<dim3(1, (3 * NN + 127) / 128, 1), 256, SMB>>>(
        p_stk, 0,
        p_wa1t, 0,
        ba1, 0,
        nf32, 0, 0, 0, 0,
        p_t16, HH / 2, 0, 0, 0, 3 * NN, HH);
    attnmeta_kernel<<<NN, TB>>>(Wa2, gmeta, bmeta);

    // 17-18: combine + output LN
    tcmm<1, 0><<<dim3(2, NP / 128, 1), 256, SMB>>>(
        p_cat, 0,
        p_wct, 0,
        bc, 0,
        p_hbuf, HH, 0, 0, 0,
        nh, 0, 0, 0, 0, NN, 2 * HH);
    outln_kernel<<<NN, TB>>>(x, gout, bout, out);
}

// round 14
// speedup vs baseline: 1.9384x; 1.9384x over previous
#include <cuda_runtime.h>
#include <cuda_fp16.h>
#include <math.h>
#include <stdint.h>

#define NN 50000
#define NP 50048          // NN padded to 128
#define RR 6
#define EE 32768
#define HH 256
#define FF 16
#define KVO 272
#define KVP 320           // 272 padded to 64-multiple
#define NHD 8
#define HDD 32
#define RH 1536

typedef __half fp16;

#if defined(__CUDA_ARCH__) && (defined(__CUDA_ARCH_FEAT_SM103_ALL) \
    || (defined(__CUDA_ARCH_SPECIFIC__) && (__CUDA_ARCH_SPECIFIC__ == 1030)) \
    || (defined(__CUDA_ARCH_FAMILY_SPECIFIC__) && (__CUDA_ARCH_FAMILY_SPECIFIC__ == 1030)))
#define HAS_TC05 1
#else
#define HAS_TC05 0
#endif

// ---------------- scratch (device globals; zero-initialized at load) ----------------
__device__ __align__(1024) fp16 g_kvin[RR * EE * KVP];
__device__ __align__(1024) fp16 g_xd[RR * EE * HH];
__device__ __align__(1024) fp16 g_qe16[(size_t)RR * EE * HH];
__device__ __align__(1024) fp16 g_k16[(size_t)RR * EE * HH];
__device__ __align__(1024) fp16 g_v16[(size_t)RR * EE * HH];
__device__ float g_sc[RR * EE * NHD], g_m[RR * NN * NHD], g_denom[RR * NN * NHD];
__device__ float g_agg[(size_t)RR * NN * HH];
__device__ __align__(1024) fp16 g_aggh[(size_t)RR * NP * HH];
__device__ __align__(1024) fp16 g_rel[(size_t)NP * RH];
__device__ float g_hbuf[NP * HH];
__device__ float g_interw[NN * NHD];
__device__ __align__(1024) fp16 g_cat[NP * 2 * HH];
__device__ __align__(1024) fp16 g_pth[3 * NP * HH];
__device__ __align__(1024) fp16 g_stk[NP * 3 * HH];
__device__ __align__(1024) fp16 g_t16[3 * NP * (HH / 2)];
// transposed weights: [Ncol][Kpad]
__device__ __align__(1024) fp16 g_wqt[RR * HH * HH];
__device__ __align__(1024) fp16 g_wkt[RR * HH * KVP];
__device__ __align__(1024) fp16 g_wvt[RR * HH * KVP];
__device__ __align__(1024) fp16 g_wmt[RR * HH * HH];
__device__ __align__(1024) fp16 g_wir1t[HH * RH];
__device__ __align__(1024) fp16 g_wmpt[3 * HH * HH];
__device__ __align__(1024) fp16 g_wa1t[(HH/2) * HH];
__device__ __align__(1024) fp16 g_wct[HH * 2 * HH];

// ---------------- common helpers ----------------
__device__ __forceinline__ float gelu_exact(float x) {
    return 0.5f * x * (1.0f + erff(x * 0.7071067811865475f));
}
__device__ __forceinline__ void store4h(float4 v, fp16* p) {
    union { __half2 h[2]; uint2 u; } U;
    U.h[0] = __halves2half2(__float2half_rn(v.x), __float2half_rn(v.y));
    U.h[1] = __halves2half2(__float2half_rn(v.z), __float2half_rn(v.w));
    *(uint2*)p = U.u;
}
__device__ __forceinline__ float4 load4h(const fp16* p) {
    union { uint2 u; __half2 h[2]; } U;
    U.u = *(const uint2*)p;
    float4 r;
    float2 a = __half22float2(U.h[0]), b = __half22float2(U.h[1]);
    r.x = a.x; r.y = a.y; r.z = b.x; r.w = b.y;
    return r;
}
__device__ __forceinline__ float dot8h(uint4 qa, uint4 ka) {
    union { uint4 u; __half2 h[4]; } Q, K;
    Q.u = qa; K.u = ka;
    float s = 0.f;
#pragma unroll
    for (int i = 0; i < 4; i++) {
        float2 q = __half22float2(Q.h[i]), k = __half22float2(K.h[i]);
        s += q.x * k.x + q.y * k.y;
    }
    return s;
}
__device__ __forceinline__ void atomicMaxF(float* addr, float v) {
    int* ai = (int*)addr;
    int old = *ai;
    while (__int_as_float(old) < v) {
        int assumed = old;
        old = atomicCAS(ai, assumed, __float_as_int(v));
        if (old == assumed) break;
    }
}
__device__ __forceinline__ float block_sum256(float v, float* sm) {
    int lane = threadIdx.x & 31, w = threadIdx.x >> 5;
#pragma unroll
    for (int o = 16; o; o >>= 1) v += __shfl_xor_sync(0xffffffffu, v, o);
    if (lane == 0) sm[w] = v;
    __syncthreads();
    float r;
    if (threadIdx.x < 8) {
        float s = sm[threadIdx.x];
#pragma unroll
        for (int o = 4; o; o >>= 1) s += __shfl_xor_sync(0xffu, s, o);
        if (threadIdx.x == 0) sm[0] = s;
    }
    __syncthreads();
    r = sm[0];
    __syncthreads();
    return r;
}
__device__ __forceinline__ uint32_t smem_u32(const void* p) {
    uint32_t a;
    asm("{ .reg .u64 t; cvta.to.shared.u64 t, %1; cvt.u32.u64 %0, t; }" : "=r"(a) : "l"(p));
    return a;
}
#define CP_ASYNC16(dst, src) \
    asm volatile("cp.async.cg.shared.global [%0], [%1], 16;" :: "r"(dst), "l"(src))
#define CP_COMMIT() asm volatile("cp.async.commit_group;")
#define CP_WAIT1()  asm volatile("cp.async.wait_group 1;")
#define CP_WAIT0()  asm volatile("cp.async.wait_group 0;")

#if HAS_TC05
#define SWZ128(o) ((o) ^ (((o) >> 3) & 0x70))
__device__ __forceinline__ uint64_t mkdesc(uint32_t addr) {
    return ((uint64_t)2 << 61) | ((uint64_t)1 << 46) | ((uint64_t)64 << 32) |
           ((uint64_t)1 << 16) | ((addr >> 4) & 0x3FFF);
}
__device__ __forceinline__ void mma_f16_ss(uint32_t d, uint64_t ad, uint64_t bd,
                                           uint32_t idesc, bool acc) {
    uint32_t en = acc ? 1u : 0u;
    asm volatile(
        "{\n\t.reg .pred p;\n\tsetp.ne.u32 p, %5, 0;\n\t"
        "tcgen05.mma.cta_group::1.kind::f16 [%0], %1, %2, %3, {%4,%4,%4,%4}, p;\n\t}"
        :: "r"(d), "l"(ad), "l"(bd), "r"(idesc), "r"(0u), "r"(en) : "memory");
}
__device__ __forceinline__ void mbar_init(uint32_t mb, uint32_t cnt) {
    asm volatile("mbarrier.init.shared.b64 [%0], %1;" :: "r"(mb), "r"(cnt) : "memory");
}
__device__ __forceinline__ void mbar_wait(uint32_t mb, int parity) {
    asm volatile(
        "{\n\t.reg .pred P1;\n\t"
        "WL_%=:\n\t"
        "mbarrier.try_wait.parity.acquire.cta.shared::cta.b64 P1, [%0], %1, 0x989680;\n\t"
        "@P1 bra.uni WD_%=;\n\t"
        "bra.uni WL_%=;\n\t"
        "WD_%=:\n\t}"
        :: "r"(mb), "r"(parity) : "memory");
}
#define LDTM_X32(r, a) \
    asm volatile( \
        "tcgen05.ld.sync.aligned.32x32b.x32.b32 " \
        "{%0, %1, %2, %3, %4, %5, %6, %7, " \
        " %8, %9, %10, %11, %12, %13, %14, %15, " \
        " %16, %17, %18, %19, %20, %21, %22, %23, " \
        " %24, %25, %26, %27, %28, %29, %30, %31}, [%32];" \
        : "=r"((r)[0]),  "=r"((r)[1]),  "=r"((r)[2]),  "=r"((r)[3]), \
          "=r"((r)[4]),  "=r"((r)[5]),  "=r"((r)[6]),  "=r"((r)[7]), \
          "=r"((r)[8]),  "=r"((r)[9]),  "=r"((r)[10]), "=r"((r)[11]), \
          "=r"((r)[12]), "=r"((r)[13]), "=r"((r)[14]), "=r"((r)[15]), \
          "=r"((r)[16]), "=r"((r)[17]), "=r"((r)[18]), "=r"((r)[19]), \
          "=r"((r)[20]), "=r"((r)[21]), "=r"((r)[22]), "=r"((r)[23]), \
          "=r"((r)[24]), "=r"((r)[25]), "=r"((r)[26]), "=r"((r)[27]), \
          "=r"((r)[28]), "=r"((r)[29]), "=r"((r)[30]), "=r"((r)[31]) \
        : "r"(a))
#else
__device__ __forceinline__ void hmma16816(float* c, const uint32_t* a, const uint32_t* b) {
    asm volatile(
        "mma.sync.aligned.m16n8k16.row.col.f32.f16.f16.f32 "
        "{%0,%1,%2,%3}, {%4,%5,%6,%7}, {%8,%9}, {%0,%1,%2,%3};"
        : "+f"(c[0]), "+f"(c[1]), "+f"(c[2]), "+f"(c[3])
        : "r"(a[0]), "r"(a[1]), "r"(a[2]), "r"(a[3]), "r"(b[0]), "r"(b[1]));
}
#define LDSM_X4(r, addr) \
    asm volatile("ldmatrix.sync.aligned.m8n8.x4.shared.b16 {%0,%1,%2,%3}, [%4];" \
        : "=r"((r)[0]), "=r"((r)[1]), "=r"((r)[2]), "=r"((r)[3]) : "r"(addr))
#endif

// ---------------- fp16 GEMM (z-batched) ----------------
// Block tile 128x128; 64-K slabs; 2-stage cp.async; 3 CTAs/SM.
// STORE: 0 = fp32 C only; 1 = fp32 C + fp16; 2 = fp16 only.
// Epilogue stores are packed: float2 for C, __half2 for Ch.
template <int ACT, int STORE>
__global__ __launch_bounds__(256, 3)
void tcmm(const fp16* __restrict__ A, long az,
          const fp16* __restrict__ B, long bz,
          const float* __restrict__ bias, int biasz,
          float* __restrict__ C, int ldc, int coff, long cz, int coffz,
          fp16* __restrict__ Ch, int ldh, int offh, long chz, int offhz,
          int M, int K) {
    extern __shared__ char smem[];
    const int tid = threadIdx.x, wid = tid >> 5, lid = tid & 31;
    const int m0 = blockIdx.y * 128;
    const int n0 = blockIdx.x * 128;
    const int z = blockIdx.z;
    A += (size_t)z * az;
    B += (size_t)z * bz;
    bias += (size_t)z * biasz;
    if (STORE != 2) { C += (size_t)z * cz; coff += z * coffz; }
    if (STORE != 0) { Ch += (size_t)z * chz; offh += z * offhz; }

#if HAS_TC05
    // ================= tcgen05 path =================
    const uint32_t sb = smem_u32(smem);
    const int ABYTES = 128 * 128;
    const int BUF = 2 * ABYTES;
    const uint32_t mbar0 = sb + 8, mbar1 = sb + 16;
    const uint32_t buf0 = sb + 1024;

    if (wid == 0) {
        asm volatile("tcgen05.alloc.cta_group::1.sync.aligned.shared::cta.b32 [%0], %1;"
                     :: "r"(sb), "r"(128u) : "memory");
        asm volatile("tcgen05.relinquish_alloc_permit.cta_group::1.sync.aligned;");
    }
    __syncthreads();
    uint32_t tmem;
    asm volatile("ld.shared.b32 %0, [%1];" : "=r"(tmem) : "r"(sb));
    if (tid == 0) { mbar_init(mbar0, 1); mbar_init(mbar1, 1); }
    __syncthreads();

    const int T = K >> 6;
    const uint32_t idesc64 = (1u << 4) | (8u << 17) | (8u << 24);

    auto load_chunk = [&](int c, uint32_t bufbase) {
        int kc = c << 6;
        for (int i = tid; i < 2048; i += 256) {
            uint32_t dst;
            const fp16* src;
            if (i < 1024) {
                int r = i >> 3, g = i & 7;
                dst = bufbase + SWZ128(r * 128 + g * 16);
                src = A + (size_t)(m0 + r) * K + kc + g * 8;
            } else {
                int j = i - 1024;
                int r = j >> 3, g = j & 7;
                dst = bufbase + ABYTES + SWZ128(r * 128 + g * 16);
                src = B + (size_t)(n0 + r) * K + kc + g * 8;
            }
            CP_ASYNC16(dst, src);
        }
        CP_COMMIT();
    };

    int ph0 = 0, ph1 = 0;
    load_chunk(0, buf0);
    for (int c = 0; c < T; c++) {
        int b = c & 1;
        if (c + 1 < T) {
            int nb = b ^ 1;
            if (c >= 1) {
                if (nb) { mbar_wait(mbar1, ph1); ph1 ^= 1; }
                else    { mbar_wait(mbar0, ph0); ph0 ^= 1; }
            }
            load_chunk(c + 1, buf0 + nb * BUF);
            CP_WAIT1();
        } else {
            CP_WAIT0();
        }
        __syncthreads();
        if (tid == 0) {
            asm volatile("fence.proxy.async.shared::cta;" ::: "memory");
            uint64_t ad = mkdesc(buf0 + b * BUF);
            uint64_t bd = mkdesc(buf0 + b * BUF + ABYTES);
#pragma unroll
            for (int ks = 0; ks < 4; ks++)
#pragma unroll
                for (int ns = 0; ns < 2; ns++)
                    mma_f16_ss(tmem + ns * 64, ad + ks * 2, bd + ns * 512 + ks * 2,
                               idesc64, (c > 0) || (ks > 0));
            asm volatile("tcgen05.commit.cta_group::1.mbarrier::arrive::one.shared::cluster.b64 [%0];"
                         :: "r"(b ? mbar1 : mbar0) : "memory");
        }
    }
    {
        int lb = (T - 1) & 1;
        if (lb) mbar_wait(mbar1, ph1); else mbar_wait(mbar0, ph0);
    }
    asm volatile("tcgen05.fence::after_thread_sync;" ::: "memory");

    {
        int row = m0 + (wid & 3) * 32 + lid;
        int colbase = (wid >> 2) * 64;
        for (int cb = 0; cb < 64; cb += 32) {
            uint32_t regs[32];
            LDTM_X32(regs, tmem + colbase + cb);
            asm volatile("tcgen05.wait::ld.sync.aligned;" ::: "memory");
            if (row < M) {
#pragma unroll
                for (int j = 0; j < 32; j += 2) {
                    int col = n0 + colbase + cb + j;
                    float v0 = __uint_as_float(regs[j]) + bias[col];
                    float v1 = __uint_as_float(regs[j + 1]) + bias[col + 1];
                    if (ACT == 1) { v0 = gelu_exact(v0); v1 = gelu_exact(v1); }
                    else if (ACT == 2) { v0 = tanhf(v0); v1 = tanhf(v1); }
                    if (STORE != 2)
                        *(float2*)&C[(size_t)row * ldc + coff + col] = make_float2(v0, v1);
                    if (STORE != 0)
                        *(__half2*)&Ch[(size_t)row * ldh + offh + col] =
                            __halves2half2(__float2half_rn(v0), __float2half_rn(v1));
                }
            }
        }
    }
    __syncthreads();
    if (wid == 0)
        asm volatile("tcgen05.dealloc.cta_group::1.sync.aligned.b32 %0, %1;"
                     :: "r"(tmem), "r"(128u));

#else
    // ================= ldmatrix + mma.sync path =================
    const uint32_t sm_u = smem_u32(smem);
    const int STG = 36864;
    const int g = lid >> 2, tig = lid & 3;
    const int wr = wid >> 2, wc = wid & 3;
    const int rowbase = wr * 64, colbase = wc * 32;
    const int S = K >> 6;

    const uint32_t a_lane = (uint32_t)(rowbase + (lid & 15)) * 144 + ((lid >> 4) << 4);
    const uint32_t b_lane = (uint32_t)(colbase + (lid & 7) + (((lid >> 4) & 1) << 3)) * 144
                          + (((lid >> 3) & 1) << 4);

    auto load_stage = [&](int s, int buf) {
        int k0 = s << 6;
        uint32_t ab = sm_u + buf * STG, bb = ab + 18432;
#pragma unroll
        for (int rep = 0; rep < 4; rep++) {
            int i = tid + 256 * rep;
            int r = i >> 3, sc = i & 7;
            CP_ASYNC16(ab + r * 144 + sc * 16, A + (size_t)(m0 + r) * K + k0 + sc * 8);
        }
#pragma unroll
        for (int rep = 0; rep < 4; rep++) {
            int i = tid + 256 * rep;
            int r = i >> 3, sc = i & 7;
            CP_ASYNC16(bb + r * 144 + sc * 16, B + (size_t)(n0 + r) * K + k0 + sc * 8);
        }
        CP_COMMIT();
    };

    float acc[4][4][4];
#pragma unroll
    for (int mf = 0; mf < 4; mf++)
#pragma unroll
        for (int nf = 0; nf < 4; nf++)
#pragma unroll
            for (int q = 0; q < 4; q++) acc[mf][nf][q] = 0.f;

    load_stage(0, 0);
    for (int s = 0; s < S; s++) {
        if (s + 1 < S) { load_stage(s + 1, (s + 1) & 1); CP_WAIT1(); }
        else CP_WAIT0();
        __syncthreads();
        uint32_t ab = sm_u + (s & 1) * STG;
        uint32_t bb = ab + 18432;
#pragma unroll
        for (int kk = 0; kk < 64; kk += 16) {
            uint32_t afr[4][4], bfr[2][4];
#pragma unroll
            for (int mf = 0; mf < 4; mf++)
                LDSM_X4(afr[mf], ab + a_lane + mf * 2304 + kk * 2);
#pragma unroll
            for (int np = 0; np < 2; np++)
                LDSM_X4(bfr[np], bb + b_lane + np * 2304 + kk * 2);
#pragma unroll
            for (int mf = 0; mf < 4; mf++)
#pragma unroll
                for (int nf = 0; nf < 4; nf++)
                    hmma16816(acc[mf][nf], afr[mf], &bfr[nf >> 1][(nf & 1) * 2]);
        }
        __syncthreads();
    }

#pragma unroll
    for (int mf = 0; mf < 4; mf++)
#pragma unroll
        for (int nf = 0; nf < 4; nf++) {
            int col0 = n0 + colbase + nf * 8 + 2 * tig;
#pragma unroll
            for (int r8 = 0; r8 < 2; r8++) {
                int row = m0 + rowbase + mf * 16 + g + r8 * 8;
                if (row < M) {
                    float v0 = acc[mf][nf][r8 * 2 + 0] + bias[col0];
                    float v1 = acc[mf][nf][r8 * 2 + 1] + bias[col0 + 1];
                    if (ACT == 1) { v0 = gelu_exact(v0); v1 = gelu_exact(v1); }
                    else if (ACT == 2) { v0 = tanhf(v0); v1 = tanhf(v1); }
                    if (STORE != 2)
                        *(float2*)&C[(size_t)row * ldc + coff + col0] = make_float2(v0, v1);
                    if (STORE != 0)
                        *(__half2*)&Ch[(size_t)row * ldh + offh + col0] =
                            __halves2half2(__float2half_rn(v0), __float2half_rn(v1));
                }
            }
        }
#endif
}

// ---------------- fused weight transpose (ALL weights, 1 launch) ----------------
__global__ void tsplit_all(const float* __restrict__ Wq, const float* __restrict__ Wk,
                           const float* __restrict__ Wv, const float* __restrict__ Wm,
                           const float* __restrict__ Wir1, const float* __restrict__ Wmp,
                           const float* __restrict__ Wa1, const float* __restrict__ Wc) {
    int idx = blockIdx.x * blockDim.x + threadIdx.x;
    int seg = blockIdx.y;
    float v;
    switch (seg) {
    case 0: {
        if (idx >= RR * HH * HH) return;
        int z = idx >> 16, w = idx & 65535, n = w >> 8, k = w & 255;
        v = Wq[(size_t)z * 65536 + k * HH + n];
        g_wqt[idx] = __float2half_rn(v);
        break; }
    case 1: {
        if (idx >= RR * HH * KVP) return;
        int z = idx / 81920, w = idx - z * 81920, n = w / KVP, k = w - n * KVP;
        v = (k < KVO) ? Wk[(size_t)z * KVO * HH + k * HH + n] : 0.f;
        g_wkt[idx] = __float2half_rn(v);
        break; }
    case 2: {
        if (idx >= RR * HH * KVP) return;
        int z = idx / 81920, w = idx - z * 81920, n = w / KVP, k = w - n * KVP;
        v = (k < KVO) ? Wv[(size_t)z * KVO * HH + k * HH + n] : 0.f;
        g_wvt[idx] = __float2half_rn(v);
        break; }
    case 3: {
        if (idx >= RR * HH * HH) return;
        int z = idx >> 16, w = idx & 65535, n = w >> 8, k = w & 255;
        v = Wm[(size_t)z * 65536 + k * HH + n];
        g_wmt[idx] = __float2half_rn(v);
        break; }
    case 4: {
        if (idx >= HH * RH) return;
        int n = idx / RH, k = idx - n * RH;
        v = Wir1[(size_t)k * HH + n];
        g_wir1t[idx] = __float2half_rn(v);
        break; }
    case 5: {
        if (idx >= 3 * HH * HH) return;
        int z = idx >> 16, w = idx & 65535, n = w >> 8, k = w & 255;
        v = Wmp[(size_t)z * 65536 + k * HH + n];
        g_wmpt[idx] = __float2half_rn(v);
        break; }
    case 6: {
        if (idx >= (HH / 2) * HH) return;
        int n = idx >> 8, k = idx & 255;
        v = Wa1[(size_t)k * (HH / 2) + n];
        g_wa1t[idx] = __float2half_rn(v);
        break; }
    default: {
        if (idx >= HH * 2 * HH) return;
        int n = idx >> 9, k = idx & 511;
        v = Wc[(size_t)k * HH + n];
        g_wct[idx] = __float2half_rn(v);
        break; }
    }
}

// ---------------- fused fills (vectorized) ----------------
__global__ void fill_all() {
    const int T14 = RR * NN * NHD / 4;
    const long T24 = (long)RR * NN * HH / 4;
    long idx = (long)blockIdx.x * blockDim.x + threadIdx.x;
    if (idx < T14) {
        ((float4*)g_m)[idx] = make_float4(-INFINITY, -INFINITY, -INFINITY, -INFINITY);
        ((float4*)g_denom)[idx] = make_float4(0.f, 0.f, 0.f, 0.f);
    } else {
        long j = idx - T14;
        if (j < T24) ((float4*)g_agg)[j] = make_float4(0.f, 0.f, 0.f, 0.f);
    }
}

// ---------------- gather (vectorized float4 -> fp16x4) ----------------
__global__ void gather_split(const float* __restrict__ x, const int* __restrict__ ei,
                             const float* __restrict__ ea) {
    long idx = (long)blockIdx.x * blockDim.x + threadIdx.x;
    const long perR = (long)EE * (KVP / 4 + HH / 4);
    if (idx >= RR * perR) return;
    int r = (int)(idx / perR);
    long rem = idx - (long)r * perR;
    if (rem < (long)EE * (KVP / 4)) {
        int e = (int)(rem / (KVP / 4)), c4 = (int)(rem - (long)e * (KVP / 4));
        int src = ei[(r * 2 + 0) * EE + e];
        float4 v;
        if (c4 < 64)      v = ((const float4*)(x + (size_t)src * HH))[c4];
        else if (c4 < 68) v = ((const float4*)(ea + ((size_t)r * EE + e) * FF))[c4 - 64];
        else              v = make_float4(0.f, 0.f, 0.f, 0.f);
        store4h(v, g_kvin + ((size_t)r * EE + e) * KVP + 4 * c4);
    } else {
        long j = rem - (long)EE * (KVP / 4);
        int e = (int)(j >> 6), c4 = (int)(j & 63);
        int dst = ei[(r * 2 + 1) * EE + e];
        float4 v = ((const float4*)(x + (size_t)dst * HH))[c4];
        store4h(v, g_xd + ((size_t)r * EE + e) * HH + 4 * c4);
    }
}

// ---------------- scores: warp per (r, e), fp16 uint4 loads ----------------
__global__ void scores_kernel(const int* __restrict__ ei, const float* __restrict__ prior) {
    int w = (blockIdx.x * blockDim.x + threadIdx.x) >> 5;
    int lane = threadIdx.x & 31;
    if (w >= RR * EE) return;
    int r = w >> 15, e = w & (EE - 1);
    const uint4* q4 = (const uint4*)(g_qe16 + ((size_t)r * EE + e) * HH);
    const uint4* k4 = (const uint4*)(g_k16  + ((size_t)r * EE + e) * HH);
    float p = dot8h(q4[lane], k4[lane]);
    p += __shfl_xor_sync(0xffffffff, p, 1);
    p += __shfl_xor_sync(0xffffffff, p, 2);
    if ((lane & 3) == 0) {
        int dst = ei[(r * 2 + 1) * EE + e];
        int h = lane >> 2;
        float s = p * 0.17677669529663687f * prior[r * NHD + h];
        g_sc[((size_t)r * EE + e) * NHD + h] = s;
        atomicMaxF(&g_m[((size_t)r * NN + dst) * NHD + h], s);
    }
}

__global__ void ex_kernel(const int* __restrict__ ei) {
    int idx = blockIdx.x * blockDim.x + threadIdx.x;
    if (idx >= RR * EE * NHD) return;
    int r = idx >> 18;
    int e = (idx >> 3) & (EE - 1), h = idx & 7;
    int dst = ei[(r * 2 + 1) * EE + e];
    float exv = expf(g_sc[idx] - g_m[((size_t)r * NN + dst) * NHD + h]);
    g_sc[idx] = exv;
    atomicAdd(&g_denom[((size_t)r * NN + dst) * NHD + h], exv);
}

// ---------------- aggregation (fp16 v, 4 atomics) ----------------
__global__ void agg_kernel(const int* __restrict__ ei) {
    long idx = (long)blockIdx.x * blockDim.x + threadIdx.x;
    if (idx >= (long)RR * EE * (HH / 4)) return;
    int r = (int)(idx >> 21);
    long w_ = idx & ((1L << 21) - 1);
    int e = (int)(w_ >> 6), c4 = (int)(w_ & 63);
    int h = c4 >> 3;
    int dst = ei[(r * 2 + 1) * EE + e];
    float w = g_sc[((size_t)r * EE + e) * NHD + h] /
              (g_denom[((size_t)r * NN + dst) * NHD + h] + 1e-16f);
    float4 vv = load4h(g_v16 + idx * 4);
    float* base = &g_agg[((size_t)r * NN + dst) * HH + 4 * c4];
    atomicAdd(base + 0, w * vv.x);
    atomicAdd(base + 1, w * vv.y);
    atomicAdd(base + 2, w * vv.z);
    atomicAdd(base + 3, w * vv.w);
}

__global__ void agg_split_kernel() {
    long idx = (long)blockIdx.x * blockDim.x + threadIdx.x;
    if (idx >= (long)RR * NN * (HH / 4)) return;
    int r = (int)(idx / ((long)NN * 64));
    long w_ = idx - (long)r * NN * 64;
    int n = (int)(w_ >> 6), c4 = (int)(w_ & 63);
    float4 v = ((const float4*)g_agg)[idx];
    store4h(v, g_aggh + ((size_t)r * NP + n) * HH + 4 * c4);
}

__global__ void interw_kernel(const float* __restrict__ Wir2, const float* __restrict__ bir2) {
    int gwarp = (blockIdx.x * blockDim.x + threadIdx.x) >> 5;
    int lane = threadIdx.x & 31;
    if (gwarp >= NN) return;
    float acc[RR] = {};
    for (int k = lane; k < HH; k += 32) {
        float hv = g_hbuf[gwarp * HH + k];
#pragma unroll
        for (int rr = 0; rr < RR; rr++) acc[rr] += hv * Wir2[k * RR + rr];
    }
#pragma unroll
    for (int rr = 0; rr < RR; rr++)
#pragma unroll
        for (int off = 16; off; off >>= 1)
            acc[rr] += __shfl_down_sync(0xffffffff, acc[rr], off);
    if (lane == 0) {
        float mx = -1e30f;
#pragma unroll
        for (int rr = 0; rr < RR; rr++) { acc[rr] += bir2[rr]; mx = fmaxf(mx, acc[rr]); }
        float s = 0.f;
#pragma unroll
        for (int rr = 0; rr < RR; rr++) { acc[rr] = expf(acc[rr] - mx); s += acc[rr]; }
        float inv = 1.f / s;
#pragma unroll
        for (int rr = 0; rr < RR; rr++) g_interw[gwarp * NHD + rr] = acc[rr] * inv;
    }
}

// fused interagg + paths (vectorized)
__global__ void postrel_kernel() {
    int idx = blockIdx.x * blockDim.x + threadIdx.x;
    if (idx >= NN * (HH / 4)) return;
    int n = idx >> 6, c4 = idx & 63;
    float4 v[RR];
#pragma unroll
    for (int rr = 0; rr < RR; rr++)
        v[rr] = load4h(g_rel + (size_t)n * RH + rr * HH + 4 * c4);
    float4 s = make_float4(0.f, 0.f, 0.f, 0.f);
#pragma unroll
    for (int rr = 0; rr < RR; rr++) {
        float w = g_interw[n * NHD + rr];
        s.x += w * v[rr].x; s.y += w * v[rr].y; s.z += w * v[rr].z; s.w += w * v[rr].w;
    }
    store4h(s, g_cat + (size_t)n * 2 * HH + 4 * c4);
    float4 p0 = make_float4(v[2].x + v[3].x, v[2].y + v[3].y, v[2].z + v[3].z, v[2].w + v[3].w);
    float4 p1 = make_float4(v[4].x + v[0].x, v[4].y + v[0].y, v[4].z + v[0].z, v[4].w + v[0].w);
    float4 p2 = make_float4(v[1].x + v[5].x, v[1].y + v[5].y, v[1].z + v[5].z, v[1].w + v[5].w);
    store4h(p0, g_pth + ((size_t)0 * NP + n) * HH + 4 * c4);
    store4h(p1, g_pth + ((size_t)1 * NP + n) * HH + 4 * c4);
    store4h(p2, g_pth + ((size_t)2 * NP + n) * HH + 4 * c4);
}

__global__ void attnmeta_kernel(const float* __restrict__ Wa2,
                                const float* __restrict__ gm, const float* __restrict__ bm_) {
    __shared__ float lg[3];
    __shared__ float sm[8];
    int n = blockIdx.x, t = threadIdx.x;
    int lane = t & 31, w = t >> 5;
    if (w < 3) {
        float a = 0.f;
        for (int j = lane; j < 128; j += 32)
            a += __half2float(g_t16[((size_t)n * 3 + w) * 128 + j]) * Wa2[j];
#pragma unroll
        for (int off = 16; off; off >>= 1) a += __shfl_down_sync(0xffffffff, a, off);
        if (lane == 0) lg[w] = a;
    }
    __syncthreads();
    float l0 = lg[0], l1 = lg[1], l2 = lg[2];
    float mx = fmaxf(l0, fmaxf(l1, l2));
    float e0 = expf(l0 - mx), e1 = expf(l1 - mx), e2 = expf(l2 - mx);
    float inv = 1.f / (e0 + e1 + e2);
    const fp16* st = g_stk + (size_t)n * 3 * HH;
    float s = (e0 * __half2float(st[t]) + e1 * __half2float(st[HH + t])
             + e2 * __half2float(st[2 * HH + t])) * inv;
    float mu = block_sum256(s, sm) * (1.f / 256.f);
    float d = s - mu;
    float var = block_sum256(d * d, sm) * (1.f / 256.f);
    float o = d * rsqrtf(var + 1e-5f) * gm[t] + bm_[t];
    g_cat[(size_t)n * 2 * HH + HH + t] = __float2half_rn(o);
}

__global__ void outln_kernel(const float* __restrict__ x, const float* __restrict__ gout,
                             const float* __restrict__ bout, float* __restrict__ out) {
    __shared__ float sm[8];
    int n = blockIdx.x, t = threadIdx.x;
    float v = x[(size_t)n * HH + t] + g_hbuf[(size_t)n * HH + t];
    float mu = block_sum256(v, sm) * (1.f / 256.f);
    float d = v - mu;
    float var = block_sum256(d * d, sm) * (1.f / 256.f);
    out[(size_t)n * HH + t] = d * rsqrtf(var + 1e-5f) * gout[t] + bout[t];
}

// ---------------- host ----------------
extern "C" void kernel_launch(void* const* d_in, const int* in_sizes, int n_in,
                              void* d_out, int out_size) {
    const float* x     = (const float*)d_in[0];
    const int*   ei    = (const int*)d_in[1];
    const float* ea    = (const float*)d_in[2];
    const float* Wq    = (const float*)d_in[3];
    const float* bq    = (const float*)d_in[4];
    const float* Wk    = (const float*)d_in[5];
    const float* bk    = (const float*)d_in[6];
    const float* Wv    = (const float*)d_in[7];
    const float* bv    = (const float*)d_in[8];
    const float* prior = (const float*)d_in[9];
    const float* Wm    = (const float*)d_in[10];
    const float* bm    = (const float*)d_in[11];
    const float* W_ir1 = (const float*)d_in[12];
    const float* b_ir1 = (const float*)d_in[13];
    const float* W_ir2 = (const float*)d_in[14];
    const float* b_ir2 = (const float*)d_in[15];
    const float* Wmp   = (const float*)d_in[16];
    const float* bmp   = (const float*)d_in[17];
    const float* Wa1   = (const float*)d_in[18];
    const float* ba1   = (const float*)d_in[19];
    const float* Wa2   = (const float*)d_in[20];
    const float* gmeta = (const float*)d_in[21];
    const float* bmeta = (const float*)d_in[22];
    const float* Wc    = (const float*)d_in[23];
    const float* bc    = (const float*)d_in[24];
    const float* gout  = (const float*)d_in[25];
    const float* bout  = (const float*)d_in[26];
    float* out = (float*)d_out;

    void* p;
#define SYM(v, s) cudaGetSymbolAddress(&p, s); auto* v = (decltype(&s[0]))p
    SYM(p_kvin, g_kvin);
    SYM(p_xd, g_xd);
    SYM(p_qe16, g_qe16); SYM(p_k16, g_k16); SYM(p_v16, g_v16);
    SYM(p_aggh, g_aggh);
    SYM(p_rel, g_rel);
    SYM(p_hbuf, g_hbuf);
    SYM(p_cat, g_cat);
    SYM(p_pth, g_pth);
    SYM(p_stk, g_stk);
    SYM(p_t16, g_t16);
    SYM(p_wqt, g_wqt);
    SYM(p_wkt, g_wkt);
    SYM(p_wvt, g_wvt);
    SYM(p_wmt, g_wmt);
    SYM(p_wir1t, g_wir1t);
    SYM(p_wmpt, g_wmpt);
    SYM(p_wa1t, g_wa1t);
    SYM(p_wct, g_wct);
#undef SYM

    const int SMB = 73728;
    cudaFuncSetAttribute((const void*)&tcmm<0, 0>, cudaFuncAttributeMaxDynamicSharedMemorySize, SMB);
    cudaFuncSetAttribute((const void*)&tcmm<0, 2>, cudaFuncAttributeMaxDynamicSharedMemorySize, SMB);
    cudaFuncSetAttribute((const void*)&tcmm<1, 2>, cudaFuncAttributeMaxDynamicSharedMemorySize, SMB);
    cudaFuncSetAttribute((const void*)&tcmm<1, 0>, cudaFuncAttributeMaxDynamicSharedMemorySize, SMB);
    cudaFuncSetAttribute((const void*)&tcmm<2, 2>, cudaFuncAttributeMaxDynamicSharedMemorySize, SMB);

    const int TB = 256;
    fp16* nh = nullptr;
    float* nf32 = nullptr;

    // 0: weight transposes
    tsplit_all<<<dim3((RR * HH * KVP + TB - 1) / TB, 8), TB>>>(Wq, Wk, Wv, Wm, W_ir1, Wmp, Wa1, Wc);
    // 1: fills
    {
        long tot = (long)RR * NN * NHD / 4 + (long)RR * NN * HH / 4;
        fill_all<<<(int)((tot + TB - 1) / TB), TB>>>();
    }
    // 2: gather
    gather_split<<<(int)(((long)RR * EE * (KVP / 4 + HH / 4) + TB - 1) / TB), TB>>>(x, ei, ea);

    // 3,4,5: q/k/v GEMMs (fp16 outputs, packed stores)
    tcmm<0, 2><<<dim3(2, EE / 128, RR), 256, SMB>>>(
        p_xd, (long)EE * HH,
        p_wqt, (long)HH * HH,
        bq, HH,
        nf32, 0, 0, 0, 0,
        p_qe16, HH, 0, (long)EE * HH, 0, EE, HH);
    tcmm<0, 2><<<dim3(2, EE / 128, RR), 256, SMB>>>(
        p_kvin, (long)EE * KVP,
        p_wkt, (long)HH * KVP,
        bk, HH,
        nf32, 0, 0, 0, 0,
        p_k16, HH, 0, (long)EE * HH, 0, EE, KVP);
    tcmm<0, 2><<<dim3(2, EE / 128, RR), 256, SMB>>>(
        p_kvin, (long)EE * KVP,
        p_wvt, (long)HH * KVP,
        bv, HH,
        nf32, 0, 0, 0, 0,
        p_v16, HH, 0, (long)EE * HH, 0, EE, KVP);

    // 6-9: attention softmax + aggregation
    scores_kernel<<<RR * EE / 8, TB>>>(ei, prior);
    ex_kernel<<<RR * EE * NHD / TB, TB>>>(ei);
    agg_kernel<<<(int)(((long)RR * EE * (HH / 4) + TB - 1) / TB), TB>>>(ei);
    agg_split_kernel<<<(int)(((long)RR * NN * (HH / 4) + TB - 1) / TB), TB>>>();

    // 10: Wm GEMM -> rel_out (fp16 only)
    tcmm<1, 2><<<dim3(2, NP / 128, RR), 256, SMB>>>(
        p_aggh, (long)NP * HH,
        p_wmt, (long)HH * HH,
        bm, HH,
        nf32, 0, 0, 0, 0,
        p_rel, RH, 0, 0, HH, NN, HH);

    // 11-13: inter-relation attention + fused post-rel
    tcmm<1, 0><<<dim3(2, NP / 128, 1), 256, SMB>>>(
        p_rel, 0,
        p_wir1t, 0,
        b_ir1, 0,
        p_hbuf, HH, 0, 0, 0,
        nh, 0, 0, 0, 0, NN, RH);
    interw_kernel<<<(NN * 32 + TB - 1) / TB, TB>>>(W_ir2, b_ir2);
    postrel_kernel<<<(NN * (HH / 4) + TB - 1) / TB, TB>>>();

    // 14-16: meta paths (fp16 outputs)
    tcmm<0, 2><<<dim3(2, NP / 128, 3), 256, SMB>>>(
        p_pth, (long)NP * HH,
        p_wmpt, (long)HH * HH,
        bmp, HH,
        nf32, 0, 0, 0, 0,
        p_stk, 3 * HH, 0, 0, HH, NN, HH);
    tcmm<2, 2><<<dim3(1, (3 * NN + 127) / 128, 1), 256, SMB>>>(
        p_stk, 0,
        p_wa1t, 0,
        ba1, 0,
        nf32, 0, 0, 0, 0,
        p_t16, HH / 2, 0, 0, 0, 3 * NN, HH);
    attnmeta_kernel<<<NN, TB>>>(Wa2, gmeta, bmeta);

    // 17-18: combine + output LN
    tcmm<1, 0><<<dim3(2, NP / 128, 1), 256, SMB>>>(
        p_cat, 0,
        p_wct, 0,
        bc, 0,
        p_hbuf, HH, 0, 0, 0,
        nh, 0, 0, 0, 0, NN, 2 * HH);
    outln_kernel<<<NN, TB>>>(x, gout, bout, out);
}